// round 2
// baseline (speedup 1.0000x reference)
#include <cuda_runtime.h>
#include <math.h>

#define BATCH  512
#define TSTEPS 55
#define CDIM   512
#define DDIM   512
#define KDIM   64
#define NL     3
#define G4D    2048      // 4*D gate width
#define HW     1536      // L*D concat width of h storage

// ---------------- scratch (static device allocations; no cudaMalloc) ----------
__device__ float g_pregate[(size_t)NL * TSTEPS * BATCH * G4D]; // x@wx + biases, accumulated with recurrent terms
__device__ float g_prer[(size_t)NL * TSTEPS * BATCH * KDIM];   // x@wr
__device__ float g_hall[(size_t)(TSTEPS + 1) * BATCH * HW];    // slab 0 = zeros (t=-1), slab t+1 = h at step t
__device__ float g_c[(size_t)NL * BATCH * DDIM];               // cell states
__device__ float g_d[(size_t)NL * BATCH * KDIM];               // decayed keys

// ---------------- init: zero state, seed keys (re-run each launch => deterministic)
__global__ void init_kernel(const float* __restrict__ init_keys) {
    int i = blockIdx.x * blockDim.x + threadIdx.x;
    if (i < BATCH * HW)        g_hall[i] = 0.0f;
    if (i < NL * BATCH * DDIM) g_c[i]   = 0.0f;
    if (i < NL * BATCH * KDIM) g_d[i]   = init_keys[i % (BATCH * KDIM)];
}

// ---------------- generic fp32 GEMM: C(+)= sum_s A_s @ W_s  ----------------
// A_s: [M, segK] rows with stride lda (segmented concat along K)
// W_s: [segK, N] row-major, stride ldb
// mode 0: C[m*ldc+n] += acc                      (recurrent gate accumulate)
// mode 1: C[((m%p1)*p2 + m/p1)*ldc + n] = acc + bias1[n] + bias2[n]   (assign w/ row permute)
#define BM  64
#define BN  128
#define BKT 16

__global__ __launch_bounds__(256)
void gemm_kernel(const float* __restrict__ A0, const float* __restrict__ A1,
                 const float* __restrict__ A2,
                 const float* __restrict__ W0, const float* __restrict__ W1,
                 const float* __restrict__ W2,
                 int nseg, int segK, int lda, int ldb,
                 float* __restrict__ C, int ldc, int N,
                 const float* __restrict__ bias1, const float* __restrict__ bias2,
                 int mode, int p1, int p2)
{
    __shared__ float As[BKT][BM + 4];
    __shared__ float Bs[BKT][BN + 4];
    int tid = threadIdx.x;
    int bm = blockIdx.y * BM;
    int bn = blockIdx.x * BN;
    int a_m = tid >> 2, a_k = (tid & 3) * 4;   // A tile: 64m x 16k, float4 along k
    int b_k = tid >> 5, b_n = (tid & 31) * 4;  // B tile: 16k x 128n, float4 along n
    int ty = tid >> 4, tx = tid & 15;          // micro-tile: rows ty*4.., cols tx*8..

    float acc[4][8];
#pragma unroll
    for (int i = 0; i < 4; i++)
#pragma unroll
        for (int j = 0; j < 8; j++) acc[i][j] = 0.0f;

    for (int s = 0; s < nseg; s++) {
        const float* A = (s == 0) ? A0 : ((s == 1) ? A1 : A2);
        const float* W = (s == 0) ? W0 : ((s == 1) ? W1 : W2);
        for (int k0 = 0; k0 < segK; k0 += BKT) {
            float4 av = *(const float4*)(A + (size_t)(bm + a_m) * lda + k0 + a_k);
            float4 bv0, bv1;
            int n = bn + b_n;
            if (n < N) {
                bv0 = *(const float4*)(W + (size_t)(k0 + b_k) * ldb + n);
                bv1 = *(const float4*)(W + (size_t)(k0 + b_k + 8) * ldb + n);
            } else {
                bv0 = make_float4(0.f, 0.f, 0.f, 0.f);
                bv1 = bv0;
            }
            __syncthreads();
            As[a_k + 0][a_m] = av.x;
            As[a_k + 1][a_m] = av.y;
            As[a_k + 2][a_m] = av.z;
            As[a_k + 3][a_m] = av.w;
            *(float4*)&Bs[b_k][b_n]     = bv0;
            *(float4*)&Bs[b_k + 8][b_n] = bv1;
            __syncthreads();
#pragma unroll
            for (int kk = 0; kk < BKT; kk++) {
                float4 a  = *(const float4*)&As[kk][ty * 4];
                float4 b0 = *(const float4*)&Bs[kk][tx * 8];
                float4 b1 = *(const float4*)&Bs[kk][tx * 8 + 4];
                float av4[4] = {a.x, a.y, a.z, a.w};
                float bv8[8] = {b0.x, b0.y, b0.z, b0.w, b1.x, b1.y, b1.z, b1.w};
#pragma unroll
                for (int i = 0; i < 4; i++)
#pragma unroll
                    for (int j = 0; j < 8; j++)
                        acc[i][j] += av4[i] * bv8[j];
            }
        }
    }

    if (mode == 0) {
#pragma unroll
        for (int i = 0; i < 4; i++) {
            int row = bm + ty * 4 + i;
            float* Cr = C + (size_t)row * ldc;
#pragma unroll
            for (int j = 0; j < 8; j++) {
                int col = bn + tx * 8 + j;
                if (col < N) Cr[col] += acc[i][j];
            }
        }
    } else {
#pragma unroll
        for (int i = 0; i < 4; i++) {
            int m = bm + ty * 4 + i;
            size_t crow = (size_t)(m % p1) * p2 + (size_t)(m / p1);
            float* Cr = C + crow * ldc;
#pragma unroll
            for (int j = 0; j < 8; j++) {
                int col = bn + tx * 8 + j;
                if (col < N) {
                    float v = acc[i][j];
                    if (bias1) v += bias1[col];
                    if (bias2) v += bias2[col];
                    Cr[col] = v;
                }
            }
        }
    }
}

// ---------------- K1: gr -> r -> d update (per layer, per step) ----------------
// gr[b,k] = prer[b,k] + sum_{j<l} hnew_j . wr_l[C+j*D + :, k] + (1/3) * hprev_j . wl_j[:, k]
// d[b,k] *= sigmoid(gr)
__global__ __launch_bounds__(256)
void k1_kernel(int l, const float* __restrict__ prer,
               const float* __restrict__ hall_cur, const float* __restrict__ hall_prev,
               const float* __restrict__ wr,
               const float* __restrict__ wl0, const float* __restrict__ wl1,
               float* __restrict__ dstate)
{
    __shared__ float hs[4][512];
    int tx = threadIdx.x;          // k index 0..63
    int ty = threadIdx.y;          // local batch 0..3
    int tid = ty * 64 + tx;
    int b = blockIdx.x * 4 + ty;
    float acc = prer[b * KDIM + tx];
    for (int j = 0; j < l; j++) {
        __syncthreads();
        for (int i = tid; i < 4 * 512; i += 256) {
            int rb = i >> 9, c = i & 511;
            hs[rb][c] = hall_cur[(size_t)(blockIdx.x * 4 + rb) * HW + j * DDIM + c];
        }
        __syncthreads();
        {
            const float* W = wr + (size_t)(CDIM + j * DDIM) * KDIM;
            float s0 = 0.f, s1 = 0.f, s2 = 0.f, s3 = 0.f;
            for (int c = 0; c < 512; c += 4) {
                s0 += hs[ty][c]     * W[(size_t)c * KDIM + tx];
                s1 += hs[ty][c + 1] * W[(size_t)(c + 1) * KDIM + tx];
                s2 += hs[ty][c + 2] * W[(size_t)(c + 2) * KDIM + tx];
                s3 += hs[ty][c + 3] * W[(size_t)(c + 3) * KDIM + tx];
            }
            acc += (s0 + s1) + (s2 + s3);
        }
        __syncthreads();
        for (int i = tid; i < 4 * 512; i += 256) {
            int rb = i >> 9, c = i & 511;
            hs[rb][c] = hall_prev[(size_t)(blockIdx.x * 4 + rb) * HW + j * DDIM + c];
        }
        __syncthreads();
        {
            const float* Wl = (j == 0) ? wl0 : wl1;
            float s0 = 0.f, s1 = 0.f, s2 = 0.f, s3 = 0.f;
            for (int c = 0; c < 512; c += 4) {
                s0 += hs[ty][c]     * Wl[(size_t)c * KDIM + tx];
                s1 += hs[ty][c + 1] * Wl[(size_t)(c + 1) * KDIM + tx];
                s2 += hs[ty][c + 2] * Wl[(size_t)(c + 2) * KDIM + tx];
                s3 += hs[ty][c + 3] * Wl[(size_t)(c + 3) * KDIM + tx];
            }
            acc += (1.0f / 3.0f) * ((s0 + s1) + (s2 + s3));
        }
    }
    float r = 1.0f / (1.0f + expf(-acc));
    dstate[b * KDIM + tx] *= r;
}

// ---------------- K2: gate nonlinearity + tanh(d @ wd) + c/h update ------------
__global__ __launch_bounds__(512)
void k2_kernel(const float* __restrict__ gate, const float* __restrict__ dvals,
               const float* __restrict__ wd, float* __restrict__ cst,
               float* __restrict__ hout)
{
    int b = blockIdx.x, dd = threadIdx.x;
    __shared__ float ds[KDIM];
    if (dd < KDIM) ds[dd] = dvals[b * KDIM + dd];
    __syncthreads();
    float s0 = 0.f, s1 = 0.f, s2 = 0.f, s3 = 0.f;
#pragma unroll
    for (int k = 0; k < KDIM; k += 4) {
        s0 += ds[k]     * wd[(size_t)k * DDIM + dd];
        s1 += ds[k + 1] * wd[(size_t)(k + 1) * DDIM + dd];
        s2 += ds[k + 2] * wd[(size_t)(k + 2) * DDIM + dd];
        s3 += ds[k + 3] * wd[(size_t)(k + 3) * DDIM + dd];
    }
    float dwd = tanhf((s0 + s1) + (s2 + s3));
    const float* g = gate + (size_t)b * G4D;
    float f  = 1.0f / (1.0f + expf(-g[dd]));
    float ii = 1.0f / (1.0f + expf(-g[DDIM + dd]));
    float o  = 1.0f / (1.0f + expf(-g[2 * DDIM + dd]));
    float cb = tanhf(g[3 * DDIM + dd]);
    float c = f * cst[(size_t)b * DDIM + dd] + ii * cb + dwd;
    cst[(size_t)b * DDIM + dd] = c;
    hout[(size_t)b * HW + dd] = o * tanhf(c);
}

// ---------------- host orchestration (graph-capturable: launches only) ---------
extern "C" void kernel_launch(void* const* d_in, const int* in_sizes, int n_in,
                              void* d_out, int out_size)
{
    (void)n_in; (void)out_size;
    const float* inputs    = (const float*)d_in[0];
    const float* init_keys = (const float*)d_in[1];
    const float *wx[NL], *wxb[NL], *wh[NL], *whb[NL], *wr[NL], *wl[NL];

    // Runtime input-order detection:
    // dict order:  idx4 = wh0_w (512*2048 = 1048576)
    // sig  order:  idx4 = wx1_w (1024*2048 = 2097152)
    bool dict_order = (in_sizes[4] == 1048576);
    if (dict_order) {
        for (int l = 0; l < NL; l++) {
            int b0 = 2 + l * 6;
            wx[l]  = (const float*)d_in[b0];
            wxb[l] = (const float*)d_in[b0 + 1];
            wh[l]  = (const float*)d_in[b0 + 2];
            whb[l] = (const float*)d_in[b0 + 3];
            wr[l]  = (const float*)d_in[b0 + 4];
            wl[l]  = (const float*)d_in[b0 + 5];
        }
    } else {
        for (int l = 0; l < NL; l++) {
            wx[l]  = (const float*)d_in[2 + 2 * l];
            wxb[l] = (const float*)d_in[3 + 2 * l];
            wh[l]  = (const float*)d_in[8 + 2 * l];
            whb[l] = (const float*)d_in[9 + 2 * l];
            wr[l]  = (const float*)d_in[14 + l];
            wl[l]  = (const float*)d_in[17 + l];
        }
    }
    const float* wd    = (const float*)d_in[20];
    const float* projw = (const float*)d_in[21];
    const float* projb = (const float*)d_in[22];
    float* out = (float*)d_out;

    float *pregate, *prer, *hall, *cst, *dst;
    cudaGetSymbolAddress((void**)&pregate, g_pregate);
    cudaGetSymbolAddress((void**)&prer,    g_prer);
    cudaGetSymbolAddress((void**)&hall,    g_hall);
    cudaGetSymbolAddress((void**)&cst,     g_c);
    cudaGetSymbolAddress((void**)&dst,     g_d);

    init_kernel<<<(BATCH * HW + 255) / 256, 256>>>(init_keys);

    // ---- time-parallel precompute of x projections (rows m = b*T + t) ----
    const int MBT = BATCH * TSTEPS;   // 28160
    for (int l = 0; l < NL; l++) {
        gemm_kernel<<<dim3(G4D / BN, MBT / BM), 256>>>(
            inputs, nullptr, nullptr, wx[l], nullptr, nullptr,
            1, CDIM, CDIM, G4D,
            pregate + (size_t)l * TSTEPS * BATCH * G4D, G4D, G4D,
            wxb[l], whb[l], 1, TSTEPS, BATCH);
        gemm_kernel<<<dim3(1, MBT / BM), 256>>>(
            inputs, nullptr, nullptr, wr[l], nullptr, nullptr,
            1, CDIM, CDIM, KDIM,
            prer + (size_t)l * TSTEPS * BATCH * KDIM, KDIM, KDIM,
            nullptr, nullptr, 1, TSTEPS, BATCH);
    }

    // ---- sequential recurrence ----
    for (int t = 0; t < TSTEPS; t++) {
        float* hall_cur  = hall + (size_t)(t + 1) * BATCH * HW;
        float* hall_prev = hall + (size_t)t * BATCH * HW;
        for (int l = 0; l < NL; l++) {
            const float* Aseg[3] = {nullptr, nullptr, nullptr};
            const float* Wseg[3] = {nullptr, nullptr, nullptr};
            int ns = 0;
            for (int j = 0; j < l; j++) {           // current-step h of earlier layers
                Aseg[ns] = hall_cur + j * DDIM;
                Wseg[ns] = wx[l] + (size_t)(CDIM + j * DDIM) * G4D;
                ns++;
            }
            if (t > 0) {                             // previous-step h of this layer
                Aseg[ns] = hall_prev + l * DDIM;
                Wseg[ns] = wh[l];
                ns++;
            }
            float* gate = pregate + ((size_t)l * TSTEPS + t) * BATCH * G4D;
            if (ns > 0) {
                gemm_kernel<<<dim3(G4D / BN, BATCH / BM), 256>>>(
                    Aseg[0], Aseg[1], Aseg[2], Wseg[0], Wseg[1], Wseg[2],
                    ns, DDIM, HW, G4D,
                    gate, G4D, G4D, nullptr, nullptr, 0, 0, 0);
            }
            k1_kernel<<<BATCH / 4, dim3(64, 4)>>>(
                l, prer + ((size_t)l * TSTEPS + t) * BATCH * KDIM,
                hall_cur, hall_prev, wr[l], wl[0], wl[1],
                dst + (size_t)l * BATCH * KDIM);
            k2_kernel<<<BATCH, DDIM>>>(
                gate, dst + (size_t)l * BATCH * KDIM, wd,
                cst + (size_t)l * BATCH * DDIM, hall_cur + l * DDIM);
        }
    }

    // ---- deferred projection: rows m = t*B + b; out[b][t][n] ----
    gemm_kernel<<<dim3(512 / BN, MBT / BM), 256>>>(
        hall + (size_t)BATCH * HW, nullptr, nullptr, projw, nullptr, nullptr,
        1, HW, HW, 512,
        out, 512, 512, projb, nullptr, 1, BATCH, TSTEPS);
}

// round 8
// speedup vs baseline: 2.0336x; 2.0336x over previous
#include <cuda_runtime.h>
#include <cuda_bf16.h>
#include <math.h>
#include <stdint.h>

#define BATCH  512
#define TSTEPS 55
#define CDIM   512
#define DDIM   512
#define KDIM   64
#define NL     3
#define G4D    2048
#define HW     1536
typedef __nv_bfloat16 bf16;

#define OFF_WX0 0u
#define OFF_WX1 1048576u
#define OFF_WX2 3145728u
#define OFF_WH0 6291456u
#define OFF_PROJ 9437184u
#define OFF_WR   10223616u
#define WTOT     10354688u

__device__ float g_pregate[(size_t)NL*TSTEPS*BATCH*G4D];
__device__ float g_prer[(size_t)TSTEPS*BATCH*256];
__device__ float g_hall[(size_t)(TSTEPS+1)*BATCH*HW];
__device__ bf16  g_hh[(size_t)(TSTEPS+1)*BATCH*HW];
__device__ bf16  g_hl[(size_t)(TSTEPS+1)*BATCH*HW];
__device__ float g_c[(size_t)NL*BATCH*DDIM];
__device__ float g_d[(size_t)NL*BATCH*KDIM];
__device__ bf16  g_xh[(size_t)BATCH*TSTEPS*CDIM];
__device__ bf16  g_xl[(size_t)BATCH*TSTEPS*CDIM];
__device__ bf16  g_pwh[WTOT];
__device__ bf16  g_pwl[WTOT];

// ---- helpers (baseline PTX only: ldmatrix, mma.sync, cp.async) ----
__device__ __forceinline__ uint32_t smem_u32(const void* p){
    uint32_t a; asm("{ .reg .u64 t; cvta.to.shared.u64 t, %1; cvt.u32.u64 %0, t; }":"=r"(a):"l"(p)); return a;
}
__device__ __forceinline__ uint32_t swz(uint32_t b){ return b ^ ((b>>3)&0x70u); }
__device__ __forceinline__ void cp16(uint32_t d, const void* s){
    asm volatile("cp.async.cg.shared.global [%0], [%1], 16;"::"r"(d),"l"(s));
}
__device__ __forceinline__ void cp_commit(){ asm volatile("cp.async.commit_group;":::"memory"); }
template<int N> __device__ __forceinline__ void cp_wait(){ asm volatile("cp.async.wait_group %0;"::"n"(N):"memory"); }
__device__ __forceinline__ void ldm4(uint32_t* r, uint32_t a){
    asm volatile("ldmatrix.sync.aligned.m8n8.x4.shared.b16 {%0,%1,%2,%3}, [%4];"
        :"=r"(r[0]),"=r"(r[1]),"=r"(r[2]),"=r"(r[3]):"r"(a));
}
__device__ __forceinline__ void mma16816(float* d, const uint32_t* a, uint32_t b0, uint32_t b1){
    asm volatile("mma.sync.aligned.m16n8k16.row.col.f32.bf16.bf16.f32 "
        "{%0,%1,%2,%3}, {%4,%5,%6,%7}, {%8,%9}, {%0,%1,%2,%3};"
        :"+f"(d[0]),"+f"(d[1]),"+f"(d[2]),"+f"(d[3])
        :"r"(a[0]),"r"(a[1]),"r"(a[2]),"r"(a[3]),"r"(b0),"r"(b1));
}

// ---- init ----
__global__ void init_kernel(const float* __restrict__ ik){
    int i = blockIdx.x*blockDim.x + threadIdx.x;
    if (i < BATCH*HW){ g_hall[i]=0.f; g_hh[i]=__float2bfloat16(0.f); g_hl[i]=__float2bfloat16(0.f); }
    if (i < NL*BATCH*DDIM) g_c[i]=0.f;
    if (i < NL*BATCH*KDIM) g_d[i]=ik[i % (BATCH*KDIM)];
    if (i < 64*512){ g_pwh[OFF_WR+192*512+i]=__float2bfloat16(0.f); g_pwl[OFF_WR+192*512+i]=__float2bfloat16(0.f); }
}

// ---- weight transpose+split: W[K,N] fp32 -> out[N,K] bf16 hi/lo ----
__global__ void wsplit_kernel(const float* __restrict__ W, bf16* __restrict__ hi, bf16* __restrict__ lo, int K, int N){
    __shared__ float t[32][33];
    int n0 = blockIdx.x*32, k0 = blockIdx.y*32;
    for (int i = threadIdx.y; i < 32; i += 8)
        t[i][threadIdx.x] = W[(size_t)(k0+i)*N + n0 + threadIdx.x];
    __syncthreads();
    for (int i = threadIdx.y; i < 32; i += 8){
        float v = t[threadIdx.x][i];
        bf16 h = __float2bfloat16(v);
        size_t o = (size_t)(n0+i)*K + k0 + threadIdx.x;
        hi[o] = h; lo[o] = __float2bfloat16(v - __bfloat162float(h));
    }
}
__global__ void xsplit_kernel(const float* __restrict__ x, bf16* __restrict__ hi, bf16* __restrict__ lo, int n){
    int i = blockIdx.x*blockDim.x + threadIdx.x;
    if (i < n){ float v = x[i]; bf16 h = __float2bfloat16(v); hi[i]=h; lo[i]=__float2bfloat16(v-__bfloat162float(h)); }
}

// ---- tensor GEMM via mma.sync: C(+)= sum_s A_s @ B_s^T, bf16x3, tile 128x128, KC=64 ----
#define KC 64
#define TILE_B 16384
#define STAGE_B 65536
#define DSMEM (1024 + 2*STAGE_B)

__device__ __forceinline__ void ldchunk(uint32_t st, int tid,
    const bf16* Ah, const bf16* Al, const bf16* Bh, const bf16* Bl,
    int bm, int bn, int lda, int ldb, int kk)
{
#pragma unroll
    for (int i = 0; i < 2; i++){
        int idx = i*512 + tid;            // 0..1023 -> (row 0..127, group 0..7)
        int row = idx>>3, g = idx&7;
        uint32_t so = swz((uint32_t)(row*128 + g*16));
        size_t ao = (size_t)(bm+row)*lda + kk + g*8;
        size_t bo = (size_t)(bn+row)*ldb + kk + g*8;
        cp16(st + so,            Ah + ao);
        cp16(st +   TILE_B + so, Al + ao);
        cp16(st + 2*TILE_B + so, Bh + bo);
        cp16(st + 3*TILE_B + so, Bl + bo);
    }
}

__global__ __launch_bounds__(512, 1)
void tgemm_kernel(const bf16* Ah0, const bf16* Al0, const bf16* Ah1, const bf16* Al1,
                  const bf16* Ah2, const bf16* Al2,
                  const bf16* Bh0, const bf16* Bl0, const bf16* Bh1, const bf16* Bl1,
                  const bf16* Bh2, const bf16* Bl2,
                  int nseg, int segK, int lda, int ldb0, int ldb1, int ldb2,
                  float* __restrict__ C, int ldc,
                  const float* __restrict__ bias1, const float* __restrict__ bias2,
                  int mode, int p1, int p2)
{
    extern __shared__ char smraw[];
    uint32_t sb = (smem_u32(smraw) + 1023u) & ~1023u;
    int tid = threadIdx.x, wid = tid>>5, lane = tid&31;
    int mw = wid & 3, nw = wid >> 2;          // 4x4 warp grid, 32x32 warp tile
    int bm = blockIdx.y*128, bn = blockIdx.x*128;

    const bf16* AH[3] = {Ah0,Ah1,Ah2}; const bf16* AL[3] = {Al0,Al1,Al2};
    const bf16* BH[3] = {Bh0,Bh1,Bh2}; const bf16* BL[3] = {Bl0,Bl1,Bl2};
    int LB[3] = {ldb0,ldb1,ldb2};
    int cps = segK / KC, nc = nseg * cps;

    float acc[2][4][4];
#pragma unroll
    for (int i=0;i<2;i++)
#pragma unroll
        for (int j=0;j<4;j++)
#pragma unroll
            for (int q=0;q<4;q++) acc[i][j][q]=0.f;

    auto load = [&](int c){
        int seg = c/cps, kk = (c%cps)*KC;
        ldchunk(sb + 1024 + (c&1)*STAGE_B, tid, AH[seg], AL[seg], BH[seg], BL[seg], bm, bn, lda, LB[seg], kk);
        cp_commit();
    };
    load(0);
    if (nc > 1) load(1);

    // precomputed lane offsets
    int a_row = (lane & 15), a_cb = (lane >> 4) << 4;
    int b_row = (lane & 7) + ((lane >> 4) << 3), b_cb = ((lane >> 3) & 1) << 4;

    for (int c = 0; c < nc; c++){
        if (c+1 < nc) cp_wait<1>(); else cp_wait<0>();
        __syncthreads();
        uint32_t st = sb + 1024 + (c&1)*STAGE_B;
#pragma unroll
        for (int t = 0; t < 3; t++){
            uint32_t Ab = st + ((t==2) ? TILE_B : 0);                 // t2: Al
            uint32_t Bb = st + 2*TILE_B + ((t==1) ? TILE_B : 0);      // t1: Bl
#pragma unroll
            for (int ks = 0; ks < 4; ks++){
                int kb = ks*32;
                uint32_t a[2][4], b[2][4];
#pragma unroll
                for (int mf = 0; mf < 2; mf++){
                    int row = mw*32 + mf*16 + a_row;
                    ldm4(a[mf], Ab + swz((uint32_t)(row*128 + kb + a_cb)));
                }
#pragma unroll
                for (int nf2 = 0; nf2 < 2; nf2++){
                    int row = nw*32 + nf2*16 + b_row;
                    ldm4(b[nf2], Bb + swz((uint32_t)(row*128 + kb + b_cb)));
                }
#pragma unroll
                for (int mf = 0; mf < 2; mf++)
#pragma unroll
                    for (int nf = 0; nf < 4; nf++)
                        mma16816(acc[mf][nf], a[mf], b[nf>>1][(nf&1)*2], b[nf>>1][(nf&1)*2+1]);
            }
        }
        __syncthreads();
        if (c+2 < nc) load(c+2);
    }

    // epilogue: c-frag lane map: rows +lane/4 and +8, cols (lane&3)*2, +1
#pragma unroll
    for (int mf = 0; mf < 2; mf++){
        int r0 = bm + mw*32 + mf*16 + (lane>>2);
#pragma unroll
        for (int half = 0; half < 2; half++){
            int rm = r0 + half*8;
            size_t crow = (mode == 0) ? (size_t)rm*ldc
                                      : ((size_t)(rm % p1)*p2 + (size_t)(rm / p1))*ldc;
            float* Cr = C + crow;
#pragma unroll
            for (int nf = 0; nf < 4; nf++){
                int col = bn + nw*32 + nf*8 + (lane&3)*2;
                float v0 = acc[mf][nf][half*2], v1 = acc[mf][nf][half*2+1];
                if (mode == 0){
                    Cr[col]   += v0;
                    Cr[col+1] += v1;
                } else {
                    if (bias1){ v0 += bias1[col]; v1 += bias1[col+1]; }
                    if (bias2){ v0 += bias2[col]; v1 += bias2[col+1]; }
                    Cr[col] = v0; Cr[col+1] = v1;
                }
            }
        }
    }
}

// ---- K1: gr -> r -> d update ----
__global__ __launch_bounds__(256)
void k1_kernel(int l, const float* __restrict__ prer,
               const float* __restrict__ hc, const float* __restrict__ hp,
               const float* __restrict__ wr, const float* __restrict__ wl0, const float* __restrict__ wl1,
               float* __restrict__ dstate)
{
    __shared__ float hs[4][512];
    int tx = threadIdx.x, ty = threadIdx.y, tid = ty*64+tx;
    int b = blockIdx.x*4 + ty;
    float acc = prer[(size_t)b*256 + tx];
    for (int j = 0; j < l; j++)
        for (int s = 0; s < 2; s++){
            const float* src = s ? hp : hc;
            const float* W = s ? ((j==0)?wl0:wl1) : (wr + (size_t)(CDIM + j*DDIM)*KDIM);
            __syncthreads();
            for (int i = tid; i < 2048; i += 256)
                hs[i>>9][i&511] = src[(size_t)(blockIdx.x*4 + (i>>9))*HW + j*DDIM + (i&511)];
            __syncthreads();
            float s0=0.f,s1=0.f,s2=0.f,s3=0.f;
            for (int c = 0; c < 512; c += 4){
                s0 += hs[ty][c]   * W[(size_t)c*KDIM+tx];
                s1 += hs[ty][c+1] * W[(size_t)(c+1)*KDIM+tx];
                s2 += hs[ty][c+2] * W[(size_t)(c+2)*KDIM+tx];
                s3 += hs[ty][c+3] * W[(size_t)(c+3)*KDIM+tx];
            }
            acc += (s ? (1.f/3.f) : 1.f) * ((s0+s1)+(s2+s3));
        }
    dstate[b*KDIM+tx] *= 1.f/(1.f+expf(-acc));
}

// ---- K2: gates + tanh(d@wd) + c/h update; writes fp32 h and bf16 hi/lo planes ----
__global__ __launch_bounds__(512)
void k2_kernel(const float* __restrict__ gate, const float* __restrict__ dvals,
               const float* __restrict__ wd, float* __restrict__ cst,
               float* __restrict__ hout, bf16* __restrict__ hh, bf16* __restrict__ hl)
{
    int b = blockIdx.x, dd = threadIdx.x;
    __shared__ float ds[KDIM];
    if (dd < KDIM) ds[dd] = dvals[b*KDIM + dd];
    __syncthreads();
    float s0=0.f,s1=0.f,s2=0.f,s3=0.f;
#pragma unroll
    for (int k = 0; k < KDIM; k += 4){
        s0 += ds[k]   * wd[(size_t)k*DDIM+dd];
        s1 += ds[k+1] * wd[(size_t)(k+1)*DDIM+dd];
        s2 += ds[k+2] * wd[(size_t)(k+2)*DDIM+dd];
        s3 += ds[k+3] * wd[(size_t)(k+3)*DDIM+dd];
    }
    float dwd = tanhf((s0+s1)+(s2+s3));
    const float* g = gate + (size_t)b*G4D;
    float f  = 1.f/(1.f+expf(-g[dd]));
    float ii = 1.f/(1.f+expf(-g[DDIM+dd]));
    float o  = 1.f/(1.f+expf(-g[2*DDIM+dd]));
    float cb = tanhf(g[3*DDIM+dd]);
    float c = f*cst[(size_t)b*DDIM+dd] + ii*cb + dwd;
    cst[(size_t)b*DDIM+dd] = c;
    float h = o*tanhf(c);
    size_t ho = (size_t)b*HW + dd;
    hout[ho] = h;
    bf16 hb = __float2bfloat16(h);
    hh[ho] = hb; hl[ho] = __float2bfloat16(h - __bfloat162float(hb));
}

// ---- host ----
static void tg(dim3 grid, const bf16* ah0,const bf16* al0,const bf16* ah1,const bf16* al1,
               const bf16* ah2,const bf16* al2,const bf16* bh0,const bf16* bl0,
               const bf16* bh1,const bf16* bl1,const bf16* bh2,const bf16* bl2,
               int nseg,int segK,int lda,int l0,int l1,int l2,float* C,int ldc,
               const float* b1,const float* b2,int mode,int p1,int p2)
{
    tgemm_kernel<<<grid, 512, DSMEM>>>(ah0,al0,ah1,al1,ah2,al2,bh0,bl0,bh1,bl1,bh2,bl2,
                                       nseg,segK,lda,l0,l1,l2,C,ldc,b1,b2,mode,p1,p2);
}

extern "C" void kernel_launch(void* const* d_in, const int* in_sizes, int n_in,
                              void* d_out, int out_size)
{
    (void)n_in; (void)out_size;
    const float* inputs    = (const float*)d_in[0];
    const float* init_keys = (const float*)d_in[1];
    const float *wx[NL], *wxb[NL], *whb[NL], *wr[NL], *wl[NL], *wh[NL];
    bool dict_order = (in_sizes[4] == 1048576);
    if (dict_order){
        for (int l = 0; l < NL; l++){
            int b0 = 2 + l*6;
            wx[l]=(const float*)d_in[b0];   wxb[l]=(const float*)d_in[b0+1];
            wh[l]=(const float*)d_in[b0+2]; whb[l]=(const float*)d_in[b0+3];
            wr[l]=(const float*)d_in[b0+4]; wl[l]=(const float*)d_in[b0+5];
        }
    } else {
        for (int l = 0; l < NL; l++){
            wx[l]=(const float*)d_in[2+2*l]; wxb[l]=(const float*)d_in[3+2*l];
            wh[l]=(const float*)d_in[8+2*l]; whb[l]=(const float*)d_in[9+2*l];
            wr[l]=(const float*)d_in[14+l];  wl[l]=(const float*)d_in[17+l];
        }
    }
    const float* wd    = (const float*)d_in[20];
    const float* projw = (const float*)d_in[21];
    const float* projb = (const float*)d_in[22];
    float* out = (float*)d_out;

    float *pregate,*prer,*hall,*cst,*dst;
    bf16 *hh,*hl,*xh,*xl,*pwh,*pwl;
    cudaGetSymbolAddress((void**)&pregate, g_pregate);
    cudaGetSymbolAddress((void**)&prer, g_prer);
    cudaGetSymbolAddress((void**)&hall, g_hall);
    cudaGetSymbolAddress((void**)&cst, g_c);
    cudaGetSymbolAddress((void**)&dst, g_d);
    cudaGetSymbolAddress((void**)&hh, g_hh);
    cudaGetSymbolAddress((void**)&hl, g_hl);
    cudaGetSymbolAddress((void**)&xh, g_xh);
    cudaGetSymbolAddress((void**)&xl, g_xl);
    cudaGetSymbolAddress((void**)&pwh, g_pwh);
    cudaGetSymbolAddress((void**)&pwl, g_pwl);

    cudaFuncSetAttribute(tgemm_kernel, cudaFuncAttributeMaxDynamicSharedMemorySize, DSMEM);

    init_kernel<<<(BATCH*HW + 255)/256, 256>>>(init_keys);
    xsplit_kernel<<<(BATCH*TSTEPS*CDIM + 255)/256, 256>>>(inputs, xh, xl, BATCH*TSTEPS*CDIM);

    const uint32_t offwx[3] = {OFF_WX0, OFF_WX1, OFF_WX2};
    const int fin[3] = {512, 1024, 1536};
    dim3 wb(32, 8);
    for (int l = 0; l < NL; l++){
        wsplit_kernel<<<dim3(64, fin[l]/32), wb>>>(wx[l], pwh+offwx[l], pwl+offwx[l], fin[l], 2048);
        wsplit_kernel<<<dim3(64, 16), wb>>>(wh[l], pwh+OFF_WH0+l*1048576u, pwl+OFF_WH0+l*1048576u, 512, 2048);
        wsplit_kernel<<<dim3(2, 16), wb>>>(wr[l], pwh+OFF_WR+l*32768u, pwl+OFF_WR+l*32768u, 512, 64);
    }
    wsplit_kernel<<<dim3(16, 48), wb>>>(projw, pwh+OFF_PROJ, pwl+OFF_PROJ, 1536, 512);

    // time-parallel precompute (output rows permuted b*T+t -> (t*B+b))
    const int MBT = BATCH*TSTEPS;
    for (int l = 0; l < NL; l++)
        tg(dim3(16, MBT/128), xh,xl,0,0,0,0, pwh+offwx[l],pwl+offwx[l],0,0,0,0,
           1, 512, 512, fin[l],0,0, pregate+(size_t)l*TSTEPS*BATCH*G4D, G4D,
           wxb[l], whb[l], 1, TSTEPS, BATCH);
    tg(dim3(2, MBT/128), xh,xl,0,0,0,0, pwh+OFF_WR,pwl+OFF_WR,0,0,0,0,
       1, 512, 512, 512,0,0, prer, 256, nullptr, nullptr, 1, TSTEPS, BATCH);

    // sequential recurrence
    for (int t = 0; t < TSTEPS; t++){
        float* ha_c = hall + (size_t)(t+1)*BATCH*HW;
        float* ha_p = hall + (size_t)t*BATCH*HW;
        bf16* hh_c = hh + (size_t)(t+1)*BATCH*HW; bf16* hl_c = hl + (size_t)(t+1)*BATCH*HW;
        bf16* hh_p = hh + (size_t)t*BATCH*HW;     bf16* hl_p = hl + (size_t)t*BATCH*HW;
        for (int l = 0; l < NL; l++){
            const bf16 *AH[3]={0,0,0},*AL[3]={0,0,0},*BH[3]={0,0,0},*BL[3]={0,0,0};
            int LB[3]={512,512,512}, ns=0;
            for (int j = 0; j < l; j++){
                AH[ns]=hh_c+j*DDIM; AL[ns]=hl_c+j*DDIM;
                BH[ns]=pwh+offwx[l]+(CDIM+j*DDIM); BL[ns]=pwl+offwx[l]+(CDIM+j*DDIM);
                LB[ns]=fin[l]; ns++;
            }
            if (t > 0){
                AH[ns]=hh_p+l*DDIM; AL[ns]=hl_p+l*DDIM;
                BH[ns]=pwh+OFF_WH0+l*1048576u; BL[ns]=pwl+OFF_WH0+l*1048576u;
                LB[ns]=512; ns++;
            }
            float* gate = pregate + ((size_t)l*TSTEPS + t)*BATCH*G4D;
            if (ns > 0)
                tg(dim3(16, 4), AH[0],AL[0],AH[1],AL[1],AH[2],AL[2],
                   BH[0],BL[0],BH[1],BL[1],BH[2],BL[2],
                   ns, 512, HW, LB[0],LB[1],LB[2], gate, G4D, nullptr,nullptr, 0,0,0);
            k1_kernel<<<BATCH/4, dim3(64,4)>>>(
                l, prer + (size_t)t*BATCH*256 + l*64, ha_c, ha_p, wr[l], wl[0], wl[1],
                dst + (size_t)l*BATCH*KDIM);
            k2_kernel<<<BATCH, DDIM>>>(
                gate, dst + (size_t)l*BATCH*KDIM, wd,
                cst + (size_t)l*BATCH*DDIM, ha_c + l*DDIM, hh_c + l*DDIM, hl_c + l*DDIM);
        }
    }

    // projection (rows t*B+b -> out[b][t][:])
    tg(dim3(4, MBT/128), hh+(size_t)BATCH*HW, hl+(size_t)BATCH*HW,0,0,0,0,
       pwh+OFF_PROJ,pwl+OFF_PROJ,0,0,0,0,
       1, 1536, HW, 1536,0,0, out, 512, projb, nullptr, 1, BATCH, TSTEPS);
}

// round 11
// speedup vs baseline: 3.1855x; 1.5664x over previous
#include <cuda_runtime.h>
#include <cuda_bf16.h>
#include <math.h>
#include <stdint.h>

#define BATCH  512
#define TSTEPS 55
#define CDIM   512
#define DDIM   512
#define KDIM   64
#define NL     3
#define G4D    2048
#define HW     1536
typedef __nv_bfloat16 bf16;

#define OFF_WX0 0u
#define OFF_WX1 1048576u
#define OFF_WX2 3145728u
#define OFF_WH0 6291456u
#define OFF_PROJ 9437184u
#define OFF_WR   10223616u
#define WTOT     10354688u

__device__ float g_pregate[(size_t)NL*TSTEPS*BATCH*G4D];
__device__ float g_prer[(size_t)TSTEPS*BATCH*256];
__device__ float g_hall[(size_t)(TSTEPS+1)*BATCH*HW];
__device__ bf16  g_hh[(size_t)(TSTEPS+1)*BATCH*HW];
__device__ bf16  g_hl[(size_t)(TSTEPS+1)*BATCH*HW];
__device__ float g_c[(size_t)NL*BATCH*DDIM];
__device__ float g_d[(size_t)NL*BATCH*KDIM];
__device__ bf16  g_xh[(size_t)BATCH*TSTEPS*CDIM];
__device__ bf16  g_xl[(size_t)BATCH*TSTEPS*CDIM];
__device__ bf16  g_pwh[WTOT];
__device__ bf16  g_pwl[WTOT];

// ---- helpers ----
__device__ __forceinline__ uint32_t smem_u32(const void* p){
    uint32_t a; asm("{ .reg .u64 t; cvta.to.shared.u64 t, %1; cvt.u32.u64 %0, t; }":"=r"(a):"l"(p)); return a;
}
__device__ __forceinline__ uint32_t swz(uint32_t b){ return b ^ ((b>>3)&0x70u); }
__device__ __forceinline__ void cp16(uint32_t d, const void* s){
    asm volatile("cp.async.cg.shared.global [%0], [%1], 16;"::"r"(d),"l"(s));
}
__device__ __forceinline__ void cp_commit(){ asm volatile("cp.async.commit_group;":::"memory"); }
template<int N> __device__ __forceinline__ void cp_wait(){ asm volatile("cp.async.wait_group %0;"::"n"(N):"memory"); }
__device__ __forceinline__ void ldm4(uint32_t* r, uint32_t a){
    asm volatile("ldmatrix.sync.aligned.m8n8.x4.shared.b16 {%0,%1,%2,%3}, [%4];"
        :"=r"(r[0]),"=r"(r[1]),"=r"(r[2]),"=r"(r[3]):"r"(a));
}
__device__ __forceinline__ void mma16816(float* d, const uint32_t* a, uint32_t b0, uint32_t b1){
    asm volatile("mma.sync.aligned.m16n8k16.row.col.f32.bf16.bf16.f32 "
        "{%0,%1,%2,%3}, {%4,%5,%6,%7}, {%8,%9}, {%0,%1,%2,%3};"
        :"+f"(d[0]),"+f"(d[1]),"+f"(d[2]),"+f"(d[3])
        :"r"(a[0]),"r"(a[1]),"r"(a[2]),"r"(a[3]),"r"(b0),"r"(b1));
}

// ---- init ----
__global__ void init_kernel(const float* __restrict__ ik){
    int i = blockIdx.x*blockDim.x + threadIdx.x;
    if (i < BATCH*HW){ g_hall[i]=0.f; g_hh[i]=__float2bfloat16(0.f); g_hl[i]=__float2bfloat16(0.f); }
    if (i < NL*BATCH*DDIM) g_c[i]=0.f;
    if (i < NL*BATCH*KDIM) g_d[i]=ik[i % (BATCH*KDIM)];
    if (i < 64*512){ g_pwh[OFF_WR+192*512+i]=__float2bfloat16(0.f); g_pwl[OFF_WR+192*512+i]=__float2bfloat16(0.f); }
}

// ---- weight transpose+split: W[K,N] fp32 -> out[N,K] bf16 hi/lo ----
__global__ void wsplit_kernel(const float* __restrict__ W, bf16* __restrict__ hi, bf16* __restrict__ lo, int K, int N){
    __shared__ float t[32][33];
    int n0 = blockIdx.x*32, k0 = blockIdx.y*32;
    for (int i = threadIdx.y; i < 32; i += 8)
        t[i][threadIdx.x] = W[(size_t)(k0+i)*N + n0 + threadIdx.x];
    __syncthreads();
    for (int i = threadIdx.y; i < 32; i += 8){
        float v = t[threadIdx.x][i];
        bf16 h = __float2bfloat16(v);
        size_t o = (size_t)(n0+i)*K + k0 + threadIdx.x;
        hi[o] = h; lo[o] = __float2bfloat16(v - __bfloat162float(h));
    }
}
__global__ void xsplit_kernel(const float* __restrict__ x, bf16* __restrict__ hi, bf16* __restrict__ lo, int n){
    int i = blockIdx.x*blockDim.x + threadIdx.x;
    if (i < n){ float v = x[i]; bf16 h = __float2bfloat16(v); hi[i]=h; lo[i]=__float2bfloat16(v-__bfloat162float(h)); }
}

// ---- tensor GEMM via mma.sync: C(+)= A @ B^T, bf16x3, 128x128 tile, KC=64, z-batched ----
#define KC 64
#define TILE_B 16384
#define STAGE_B 65536
#define DSMEM (1024 + 2*STAGE_B)

__device__ __forceinline__ void ldchunk(uint32_t st, int tid,
    const bf16* Ah, const bf16* Al, const bf16* Bh, const bf16* Bl,
    int bm, int bn, int lda, int ldb, int kk)
{
#pragma unroll
    for (int i = 0; i < 2; i++){
        int idx = i*512 + tid;
        int row = idx>>3, g = idx&7;
        uint32_t so = swz((uint32_t)(row*128 + g*16));
        size_t ao = (size_t)(bm+row)*lda + kk + g*8;
        size_t bo = (size_t)(bn+row)*ldb + kk + g*8;
        cp16(st + so,            Ah + ao);
        cp16(st +   TILE_B + so, Al + ao);
        cp16(st + 2*TILE_B + so, Bh + bo);
        cp16(st + 3*TILE_B + so, Bl + bo);
    }
}

__global__ __launch_bounds__(512, 1)
void tgemm_kernel(const bf16* Ah, const bf16* Al, const bf16* Bh, const bf16* Bl,
                  int az, int bz, long long cz,
                  int segK, int lda, int ldb,
                  float* C, int ldc,
                  const float* __restrict__ bias1, const float* __restrict__ bias2,
                  int mode, int p1, int p2)
{
    extern __shared__ char smraw[];
    uint32_t sb = (smem_u32(smraw) + 1023u) & ~1023u;
    int tid = threadIdx.x, wid = tid>>5, lane = tid&31;
    int mw = wid & 3, nw = wid >> 2;
    int bm = blockIdx.y*128, bn = blockIdx.x*128;
    int z = blockIdx.z;
    Ah += (size_t)z*az; Al += (size_t)z*az;
    Bh += (size_t)z*bz; Bl += (size_t)z*bz;
    C  += (size_t)z*cz;
    int nc = segK / KC;

    float acc[2][4][4];
#pragma unroll
    for (int i=0;i<2;i++)
#pragma unroll
        for (int j=0;j<4;j++)
#pragma unroll
            for (int q=0;q<4;q++) acc[i][j][q]=0.f;

    auto load = [&](int c){
        ldchunk(sb + 1024 + (c&1)*STAGE_B, tid, Ah, Al, Bh, Bl, bm, bn, lda, ldb, c*KC);
        cp_commit();
    };
    load(0);
    if (nc > 1) load(1);

    int a_row = (lane & 15), a_cb = (lane >> 4) << 4;
    int b_row = (lane & 7) + ((lane >> 4) << 3), b_cb = ((lane >> 3) & 1) << 4;

    for (int c = 0; c < nc; c++){
        if (c+1 < nc) cp_wait<1>(); else cp_wait<0>();
        __syncthreads();
        uint32_t st = sb + 1024 + (c&1)*STAGE_B;
#pragma unroll
        for (int ks = 0; ks < 4; ks++){
            int kb = ks*32;
            uint32_t ah[2][4], al[2][4], bh[2][4], bl[2][4];
#pragma unroll
            for (int mf = 0; mf < 2; mf++){
                uint32_t off = swz((uint32_t)((mw*32 + mf*16 + a_row)*128 + kb + a_cb));
                ldm4(ah[mf], st + off);
                ldm4(al[mf], st + TILE_B + off);
            }
#pragma unroll
            for (int nf2 = 0; nf2 < 2; nf2++){
                uint32_t off = swz((uint32_t)((nw*32 + nf2*16 + b_row)*128 + kb + b_cb));
                ldm4(bh[nf2], st + 2*TILE_B + off);
                ldm4(bl[nf2], st + 3*TILE_B + off);
            }
#pragma unroll
            for (int mf = 0; mf < 2; mf++)
#pragma unroll
                for (int nf = 0; nf < 4; nf++){
                    uint32_t h0 = bh[nf>>1][(nf&1)*2], h1 = bh[nf>>1][(nf&1)*2+1];
                    uint32_t l0 = bl[nf>>1][(nf&1)*2], l1 = bl[nf>>1][(nf&1)*2+1];
                    mma16816(acc[mf][nf], ah[mf], h0, h1);
                    mma16816(acc[mf][nf], ah[mf], l0, l1);
                    mma16816(acc[mf][nf], al[mf], h0, h1);
                }
        }
        __syncthreads();
        if (c+2 < nc) load(c+2);
    }

#pragma unroll
    for (int mf = 0; mf < 2; mf++){
        int r0 = bm + mw*32 + mf*16 + (lane>>2);
#pragma unroll
        for (int half = 0; half < 2; half++){
            int rm = r0 + half*8;
            size_t crow = (mode == 0) ? (size_t)rm*ldc
                                      : ((size_t)(rm % p1)*p2 + (size_t)(rm / p1))*ldc;
            float* Cr = C + crow;
#pragma unroll
            for (int nf = 0; nf < 4; nf++){
                int col = bn + nw*32 + nf*8 + (lane&3)*2;
                float v0 = acc[mf][nf][half*2], v1 = acc[mf][nf][half*2+1];
                if (mode == 0){
                    Cr[col]   += v0;
                    Cr[col+1] += v1;
                } else {
                    if (bias1){ v0 += bias1[col]; v1 += bias1[col+1]; }
                    if (bias2){ v0 += bias2[col]; v1 += bias2[col+1]; }
                    Cr[col] = v0; Cr[col+1] = v1;
                }
            }
        }
    }
}

// ---- fused K1+K2: gr->r->d, then gates + tanh(d@wd) + c/h update ----
__global__ __launch_bounds__(512)
void k12_kernel(int l, const float* __restrict__ prer,
                const float* __restrict__ hc, const float* __restrict__ hp,
                const float* __restrict__ wr, const float* __restrict__ wl0, const float* __restrict__ wl1,
                const float* __restrict__ gate, const float* __restrict__ wd,
                float* __restrict__ cst, float* __restrict__ dstate,
                float* __restrict__ hout, bf16* __restrict__ hh, bf16* __restrict__ hl)
{
    __shared__ float hs[4][512];
    __shared__ float red[4][64];
    __shared__ float dsm[4][64];
    int tid = threadIdx.x;
    int tx = tid & 63, ty = (tid>>6)&3, e = tid>>8;
    int b0 = blockIdx.x*4;
    float acc = 0.f;
    if (e == 0) acc = prer[(size_t)(b0+ty)*256 + tx];
    for (int j = 0; j < l; j++)
        for (int s = 0; s < 2; s++){
            const float* src = s ? hp : hc;
            const float* W = s ? ((j==0)?wl0:wl1) : (wr + (size_t)(CDIM + j*DDIM)*KDIM);
            __syncthreads();
            for (int i = tid; i < 2048; i += 512)
                hs[i>>9][i&511] = src[(size_t)(b0 + (i>>9))*HW + j*DDIM + (i&511)];
            __syncthreads();
            int cb = e*256;
            float p0=0.f,p1=0.f,p2=0.f,p3=0.f;
            for (int c = 0; c < 256; c += 4){
                p0 += hs[ty][cb+c]  *W[(size_t)(cb+c)*KDIM+tx];
                p1 += hs[ty][cb+c+1]*W[(size_t)(cb+c+1)*KDIM+tx];
                p2 += hs[ty][cb+c+2]*W[(size_t)(cb+c+2)*KDIM+tx];
                p3 += hs[ty][cb+c+3]*W[(size_t)(cb+c+3)*KDIM+tx];
            }
            float part = (p0+p1)+(p2+p3);
            if (e == 1) red[ty][tx] = part;
            __syncthreads();
            if (e == 0) acc += (s ? (1.f/3.f) : 1.f) * (part + red[ty][tx]);
        }
    __syncthreads();
    if (e == 0){
        float r = 1.f/(1.f+expf(-acc));
        size_t di = (size_t)(b0+ty)*KDIM + tx;
        float dn = dstate[di]*r;
        dstate[di] = dn;
        dsm[ty][tx] = dn;
    }
    __syncthreads();
    int dd = tid;
    for (int r = 0; r < 4; r++){
        int b = b0 + r;
        float s0=0.f,s1=0.f,s2=0.f,s3=0.f;
#pragma unroll
        for (int k = 0; k < KDIM; k += 4){
            s0 += dsm[r][k]  *wd[(size_t)k*DDIM+dd];
            s1 += dsm[r][k+1]*wd[(size_t)(k+1)*DDIM+dd];
            s2 += dsm[r][k+2]*wd[(size_t)(k+2)*DDIM+dd];
            s3 += dsm[r][k+3]*wd[(size_t)(k+3)*DDIM+dd];
        }
        float dwd = tanhf((s0+s1)+(s2+s3));
        const float* g = gate + (size_t)b*G4D;
        float f  = 1.f/(1.f+expf(-g[dd]));
        float ii = 1.f/(1.f+expf(-g[DDIM+dd]));
        float o  = 1.f/(1.f+expf(-g[2*DDIM+dd]));
        float cb = tanhf(g[3*DDIM+dd]);
        size_t ci = (size_t)b*DDIM + dd;
        float c = f*cst[ci] + ii*cb + dwd;
        cst[ci] = c;
        float h = o*tanhf(c);
        size_t ho = (size_t)b*HW + dd;
        hout[ho] = h;
        bf16 hb = __float2bfloat16(h);
        hh[ho] = hb; hl[ho] = __float2bfloat16(h - __bfloat162float(hb));
    }
}

// ---- host ----
extern "C" void kernel_launch(void* const* d_in, const int* in_sizes, int n_in,
                              void* d_out, int out_size)
{
    (void)n_in; (void)out_size;
    const float* inputs    = (const float*)d_in[0];
    const float* init_keys = (const float*)d_in[1];
    const float *wx[NL], *wxb[NL], *whb[NL], *wr[NL], *wl[NL], *wh[NL];
    bool dict_order = (in_sizes[4] == 1048576);
    if (dict_order){
        for (int l = 0; l < NL; l++){
            int b0 = 2 + l*6;
            wx[l]=(const float*)d_in[b0];   wxb[l]=(const float*)d_in[b0+1];
            wh[l]=(const float*)d_in[b0+2]; whb[l]=(const float*)d_in[b0+3];
            wr[l]=(const float*)d_in[b0+4]; wl[l]=(const float*)d_in[b0+5];
        }
    } else {
        for (int l = 0; l < NL; l++){
            wx[l]=(const float*)d_in[2+2*l]; wxb[l]=(const float*)d_in[3+2*l];
            wh[l]=(const float*)d_in[8+2*l]; whb[l]=(const float*)d_in[9+2*l];
            wr[l]=(const float*)d_in[14+l];  wl[l]=(const float*)d_in[17+l];
        }
    }
    const float* wd    = (const float*)d_in[20];
    const float* projw = (const float*)d_in[21];
    const float* projb = (const float*)d_in[22];
    float* out = (float*)d_out;

    float *pregate,*prer,*hall,*cst,*dst;
    bf16 *hh,*hl,*xh,*xl,*pwh,*pwl;
    cudaGetSymbolAddress((void**)&pregate, g_pregate);
    cudaGetSymbolAddress((void**)&prer, g_prer);
    cudaGetSymbolAddress((void**)&hall, g_hall);
    cudaGetSymbolAddress((void**)&cst, g_c);
    cudaGetSymbolAddress((void**)&dst, g_d);
    cudaGetSymbolAddress((void**)&hh, g_hh);
    cudaGetSymbolAddress((void**)&hl, g_hl);
    cudaGetSymbolAddress((void**)&xh, g_xh);
    cudaGetSymbolAddress((void**)&xl, g_xl);
    cudaGetSymbolAddress((void**)&pwh, g_pwh);
    cudaGetSymbolAddress((void**)&pwl, g_pwl);

    cudaFuncSetAttribute(tgemm_kernel, cudaFuncAttributeMaxDynamicSharedMemorySize, DSMEM);

    init_kernel<<<(BATCH*HW + 255)/256, 256>>>(init_keys);
    xsplit_kernel<<<(BATCH*TSTEPS*CDIM + 255)/256, 256>>>(inputs, xh, xl, BATCH*TSTEPS*CDIM);

    const uint32_t offwx[3] = {OFF_WX0, OFF_WX1, OFF_WX2};
    const int fin[3] = {512, 1024, 1536};
    dim3 wb(32, 8);
    for (int l = 0; l < NL; l++){
        wsplit_kernel<<<dim3(64, fin[l]/32), wb>>>(wx[l], pwh+offwx[l], pwl+offwx[l], fin[l], 2048);
        wsplit_kernel<<<dim3(64, 16), wb>>>(wh[l], pwh+OFF_WH0+l*1048576u, pwl+OFF_WH0+l*1048576u, 512, 2048);
        wsplit_kernel<<<dim3(2, 16), wb>>>(wr[l], pwh+OFF_WR+l*32768u, pwl+OFF_WR+l*32768u, 512, 64);
    }
    wsplit_kernel<<<dim3(16, 48), wb>>>(projw, pwh+OFF_PROJ, pwl+OFF_PROJ, 1536, 512);

    const int MBT = BATCH*TSTEPS;
    const long long SLAB = (long long)TSTEPS*BATCH*G4D;
    // time-parallel precompute (rows b*T+t -> slab row t*B+b)
    for (int l = 0; l < NL; l++)
        tgemm_kernel<<<dim3(16, MBT/128, 1), 512, DSMEM>>>(
            xh, xl, pwh+offwx[l], pwl+offwx[l], 0,0,0,
            512, 512, fin[l], pregate + (size_t)l*SLAB, G4D,
            wxb[l], whb[l], 1, TSTEPS, BATCH);
    tgemm_kernel<<<dim3(2, MBT/128, 1), 512, DSMEM>>>(
        xh, xl, pwh+OFF_WR, pwl+OFF_WR, 0,0,0,
        512, 512, 512, prer, 256, nullptr, nullptr, 1, TSTEPS, BATCH);

    // sequential recurrence
    for (int t = 0; t < TSTEPS; t++){
        float* ha_c = hall + (size_t)(t+1)*BATCH*HW;
        float* ha_p = hall + (size_t)t*BATCH*HW;
        bf16* hh_c = hh + (size_t)(t+1)*BATCH*HW; bf16* hl_c = hl + (size_t)(t+1)*BATCH*HW;
        bf16* hh_p = hh + (size_t)t*BATCH*HW;     bf16* hl_p = hl + (size_t)t*BATCH*HW;
        float* gate_t = pregate + (size_t)t*BATCH*G4D;   // layer l slab at + l*SLAB

        if (t > 0)   // all 3 layers' h_prev @ wh, z-batched
            tgemm_kernel<<<dim3(16, 4, 3), 512, DSMEM>>>(
                hh_p, hl_p, pwh+OFF_WH0, pwl+OFF_WH0,
                DDIM, 1048576, SLAB,
                512, HW, 512, gate_t, G4D, nullptr, nullptr, 0, 0, 0);

        for (int l = 0; l < NL; l++){
            if (l == 1)      // h0_new @ wx1[C:]
                tgemm_kernel<<<dim3(16, 4, 1), 512, DSMEM>>>(
                    hh_c, hl_c, pwh+OFF_WX1+CDIM, pwl+OFF_WX1+CDIM, 0,0,0,
                    512, HW, 1024, gate_t + 1*SLAB, G4D, nullptr, nullptr, 0, 0, 0);
            else if (l == 2) // [h0_new h1_new] @ wx2[C:]  (contiguous K=1024)
                tgemm_kernel<<<dim3(16, 4, 1), 512, DSMEM>>>(
                    hh_c, hl_c, pwh+OFF_WX2+CDIM, pwl+OFF_WX2+CDIM, 0,0,0,
                    1024, HW, 1536, gate_t + 2*SLAB, G4D, nullptr, nullptr, 0, 0, 0);
            k12_kernel<<<BATCH/4, 512>>>(
                l, prer + (size_t)t*BATCH*256 + l*64, ha_c, ha_p,
                wr[l], wl[0], wl[1],
                gate_t + (size_t)l*SLAB, wd,
                cst + (size_t)l*BATCH*DDIM, dst + (size_t)l*BATCH*KDIM,
                ha_c + l*DDIM, hh_c + l*DDIM, hl_c + l*DDIM);
        }
    }

    // projection (rows t*B+b -> out[b][t][:])
    tgemm_kernel<<<dim3(4, MBT/128, 1), 512, DSMEM>>>(
        hh + (size_t)BATCH*HW, hl + (size_t)BATCH*HW, pwh+OFF_PROJ, pwl+OFF_PROJ, 0,0,0,
        1536, HW, 1536, out, 512, projb, nullptr, 1, BATCH, TSTEPS);
}

// round 12
// speedup vs baseline: 3.8259x; 1.2010x over previous
#include <cuda_runtime.h>
#include <cuda_bf16.h>
#include <math.h>
#include <stdint.h>

#define BATCH  512
#define TSTEPS 55
#define CDIM   512
#define DDIM   512
#define KDIM   64
#define NL     3
#define G4D    2048
#define HW     1536
typedef __nv_bfloat16 bf16;

#define OFF_WX0 0u
#define OFF_WX1 1048576u
#define OFF_WX2 3145728u
#define OFF_WH0 6291456u
#define OFF_PROJ 9437184u
#define OFF_WR   10223616u
#define WTOT     10354688u

__device__ float g_pregate[(size_t)NL*TSTEPS*BATCH*G4D];
__device__ float g_whbuf[(size_t)NL*BATCH*G4D];
__device__ float g_prer[(size_t)TSTEPS*BATCH*256];
__device__ float g_hall[(size_t)(TSTEPS+1)*BATCH*HW];
__device__ bf16  g_hh[(size_t)(TSTEPS+1)*BATCH*HW];
__device__ bf16  g_hl[(size_t)(TSTEPS+1)*BATCH*HW];
__device__ float g_c[(size_t)NL*BATCH*DDIM];
__device__ float g_d[(size_t)NL*BATCH*KDIM];
__device__ bf16  g_xh[(size_t)BATCH*TSTEPS*CDIM];
__device__ bf16  g_xl[(size_t)BATCH*TSTEPS*CDIM];
__device__ bf16  g_pwh[WTOT];
__device__ bf16  g_pwl[WTOT];

// ---- helpers ----
__device__ __forceinline__ uint32_t smem_u32(const void* p){
    uint32_t a; asm("{ .reg .u64 t; cvta.to.shared.u64 t, %1; cvt.u32.u64 %0, t; }":"=r"(a):"l"(p)); return a;
}
__device__ __forceinline__ uint32_t swz(uint32_t b){ return b ^ ((b>>3)&0x70u); }
__device__ __forceinline__ void cp16(uint32_t d, const void* s){
    asm volatile("cp.async.cg.shared.global [%0], [%1], 16;"::"r"(d),"l"(s));
}
__device__ __forceinline__ void cp_commit(){ asm volatile("cp.async.commit_group;":::"memory"); }
template<int N> __device__ __forceinline__ void cp_wait(){ asm volatile("cp.async.wait_group %0;"::"n"(N):"memory"); }
__device__ __forceinline__ void ldm4(uint32_t* r, uint32_t a){
    asm volatile("ldmatrix.sync.aligned.m8n8.x4.shared.b16 {%0,%1,%2,%3}, [%4];"
        :"=r"(r[0]),"=r"(r[1]),"=r"(r[2]),"=r"(r[3]):"r"(a));
}
__device__ __forceinline__ void mma16816(float* d, const uint32_t* a, uint32_t b0, uint32_t b1){
    asm volatile("mma.sync.aligned.m16n8k16.row.col.f32.bf16.bf16.f32 "
        "{%0,%1,%2,%3}, {%4,%5,%6,%7}, {%8,%9}, {%0,%1,%2,%3};"
        :"+f"(d[0]),"+f"(d[1]),"+f"(d[2]),"+f"(d[3])
        :"r"(a[0]),"r"(a[1]),"r"(a[2]),"r"(a[3]),"r"(b0),"r"(b1));
}

// ---- init ----
__global__ void init_kernel(const float* __restrict__ ik){
    int i = blockIdx.x*blockDim.x + threadIdx.x;
    if (i < BATCH*HW){ g_hall[i]=0.f; g_hh[i]=__float2bfloat16(0.f); g_hl[i]=__float2bfloat16(0.f); }
    if (i < NL*BATCH*DDIM) g_c[i]=0.f;
    if (i < NL*BATCH*KDIM) g_d[i]=ik[i % (BATCH*KDIM)];
    if (i < 64*512){ g_pwh[OFF_WR+192*512+i]=__float2bfloat16(0.f); g_pwl[OFF_WR+192*512+i]=__float2bfloat16(0.f); }
}

// ---- weight transpose+split: W[K,N] fp32 -> out[N,K] bf16 hi/lo ----
__global__ void wsplit_kernel(const float* __restrict__ W, bf16* __restrict__ hi, bf16* __restrict__ lo, int K, int N){
    __shared__ float t[32][33];
    int n0 = blockIdx.x*32, k0 = blockIdx.y*32;
    for (int i = threadIdx.y; i < 32; i += 8)
        t[i][threadIdx.x] = W[(size_t)(k0+i)*N + n0 + threadIdx.x];
    __syncthreads();
    for (int i = threadIdx.y; i < 32; i += 8){
        float v = t[threadIdx.x][i];
        bf16 h = __float2bfloat16(v);
        size_t o = (size_t)(n0+i)*K + k0 + threadIdx.x;
        hi[o] = h; lo[o] = __float2bfloat16(v - __bfloat162float(h));
    }
}
__global__ void xsplit_kernel(const float* __restrict__ x, bf16* __restrict__ hi, bf16* __restrict__ lo, int n){
    int i = blockIdx.x*blockDim.x + threadIdx.x;
    if (i < n){ float v = x[i]; bf16 h = __float2bfloat16(v); hi[i]=h; lo[i]=__float2bfloat16(v-__bfloat162float(h)); }
}

// ---- tensor GEMM via mma.sync: C(+)= A @ B^T, bf16x3, 128x128 tile, KC=64, z-batched ----
// z==1 && BhB!=null selects alternate B plane/ldb (mixed z-batch).
#define KC 64
#define TILE_B 16384
#define STAGE_B 65536
#define DSMEM (1024 + 2*STAGE_B)

__device__ __forceinline__ void ldchunk(uint32_t st, int tid,
    const bf16* Ah, const bf16* Al, const bf16* Bh, const bf16* Bl,
    int bm, int bn, int lda, int ldb, int kk)
{
#pragma unroll
    for (int i = 0; i < 2; i++){
        int idx = i*512 + tid;
        int row = idx>>3, g = idx&7;
        uint32_t so = swz((uint32_t)(row*128 + g*16));
        size_t ao = (size_t)(bm+row)*lda + kk + g*8;
        size_t bo = (size_t)(bn+row)*ldb + kk + g*8;
        cp16(st + so,            Ah + ao);
        cp16(st +   TILE_B + so, Al + ao);
        cp16(st + 2*TILE_B + so, Bh + bo);
        cp16(st + 3*TILE_B + so, Bl + bo);
    }
}

__global__ __launch_bounds__(512, 1)
void tgemm_kernel(const bf16* Ah, const bf16* Al, const bf16* Bh, const bf16* Bl,
                  const bf16* BhB, const bf16* BlB, int ldbB,
                  int az, int bz, long long cz,
                  int segK, int lda, int ldb,
                  float* C, int ldc,
                  const float* __restrict__ bias1, const float* __restrict__ bias2,
                  int mode, int p1, int p2)
{
    extern __shared__ char smraw[];
    uint32_t sb = (smem_u32(smraw) + 1023u) & ~1023u;
    int tid = threadIdx.x, wid = tid>>5, lane = tid&31;
    int mw = wid & 3, nw = wid >> 2;
    int bm = blockIdx.y*128, bn = blockIdx.x*128;
    int z = blockIdx.z;
    if (z == 1 && BhB){ Bh = BhB; Bl = BlB; ldb = ldbB; }
    else { Bh += (size_t)z*bz; Bl += (size_t)z*bz; }
    Ah += (size_t)z*az; Al += (size_t)z*az;
    C  += (size_t)z*cz;
    int nc = segK / KC;

    float acc[2][4][4];
#pragma unroll
    for (int i=0;i<2;i++)
#pragma unroll
        for (int j=0;j<4;j++)
#pragma unroll
            for (int q=0;q<4;q++) acc[i][j][q]=0.f;

    auto load = [&](int c){
        ldchunk(sb + 1024 + (c&1)*STAGE_B, tid, Ah, Al, Bh, Bl, bm, bn, lda, ldb, c*KC);
        cp_commit();
    };
    load(0);
    if (nc > 1) load(1);

    int a_row = (lane & 15), a_cb = (lane >> 4) << 4;
    int b_row = (lane & 7) + ((lane >> 4) << 3), b_cb = ((lane >> 3) & 1) << 4;

    for (int c = 0; c < nc; c++){
        if (c+1 < nc) cp_wait<1>(); else cp_wait<0>();
        __syncthreads();
        uint32_t st = sb + 1024 + (c&1)*STAGE_B;
#pragma unroll
        for (int ks = 0; ks < 4; ks++){
            int kb = ks*32;
            uint32_t ah[2][4], al[2][4], bh[2][4], bl[2][4];
#pragma unroll
            for (int mf = 0; mf < 2; mf++){
                uint32_t off = swz((uint32_t)((mw*32 + mf*16 + a_row)*128 + kb + a_cb));
                ldm4(ah[mf], st + off);
                ldm4(al[mf], st + TILE_B + off);
            }
#pragma unroll
            for (int nf2 = 0; nf2 < 2; nf2++){
                uint32_t off = swz((uint32_t)((nw*32 + nf2*16 + b_row)*128 + kb + b_cb));
                ldm4(bh[nf2], st + 2*TILE_B + off);
                ldm4(bl[nf2], st + 3*TILE_B + off);
            }
#pragma unroll
            for (int mf = 0; mf < 2; mf++)
#pragma unroll
                for (int nf = 0; nf < 4; nf++){
                    uint32_t h0 = bh[nf>>1][(nf&1)*2], h1 = bh[nf>>1][(nf&1)*2+1];
                    uint32_t l0 = bl[nf>>1][(nf&1)*2], l1 = bl[nf>>1][(nf&1)*2+1];
                    mma16816(acc[mf][nf], ah[mf], h0, h1);
                    mma16816(acc[mf][nf], ah[mf], l0, l1);
                    mma16816(acc[mf][nf], al[mf], h0, h1);
                }
        }
        __syncthreads();
        if (c+2 < nc) load(c+2);
    }

#pragma unroll
    for (int mf = 0; mf < 2; mf++){
        int r0 = bm + mw*32 + mf*16 + (lane>>2);
#pragma unroll
        for (int half = 0; half < 2; half++){
            int rm = r0 + half*8;
            size_t crow = (mode == 0) ? (size_t)rm*ldc
                                      : ((size_t)(rm % p1)*p2 + (size_t)(rm / p1))*ldc;
            float* Cr = C + crow;
#pragma unroll
            for (int nf = 0; nf < 4; nf++){
                int col = bn + nw*32 + nf*8 + (lane&3)*2;
                float v0 = acc[mf][nf][half*2], v1 = acc[mf][nf][half*2+1];
                if (mode == 0){
                    Cr[col]   += v0;
                    Cr[col+1] += v1;
                } else {
                    if (bias1){ v0 += bias1[col]; v1 += bias1[col+1]; }
                    if (bias2){ v0 += bias2[col]; v1 += bias2[col+1]; }
                    Cr[col] = v0; Cr[col+1] = v1;
                }
            }
        }
    }
}

// ---- fused K1+K2 (adds optional wh-buffer gate term) ----
__global__ __launch_bounds__(512)
void k12_kernel(int l, const float* __restrict__ prer,
                const float* __restrict__ hc, const float* __restrict__ hp,
                const float* __restrict__ wr, const float* __restrict__ wl0, const float* __restrict__ wl1,
                const float* __restrict__ gate, const float* __restrict__ whg,
                const float* __restrict__ wd,
                float* __restrict__ cst, float* __restrict__ dstate,
                float* __restrict__ hout, bf16* __restrict__ hh, bf16* __restrict__ hl)
{
    __shared__ float hs[4][512];
    __shared__ float red[4][64];
    __shared__ float dsm[4][64];
    int tid = threadIdx.x;
    int tx = tid & 63, ty = (tid>>6)&3, e = tid>>8;
    int b0 = blockIdx.x*4;
    float acc = 0.f;
    if (e == 0) acc = prer[(size_t)(b0+ty)*256 + tx];
    for (int j = 0; j < l; j++)
        for (int s = 0; s < 2; s++){
            const float* src = s ? hp : hc;
            const float* W = s ? ((j==0)?wl0:wl1) : (wr + (size_t)(CDIM + j*DDIM)*KDIM);
            __syncthreads();
            for (int i = tid; i < 2048; i += 512)
                hs[i>>9][i&511] = src[(size_t)(b0 + (i>>9))*HW + j*DDIM + (i&511)];
            __syncthreads();
            int cb = e*256;
            float p0=0.f,p1=0.f,p2=0.f,p3=0.f;
            for (int c = 0; c < 256; c += 4){
                p0 += hs[ty][cb+c]  *W[(size_t)(cb+c)*KDIM+tx];
                p1 += hs[ty][cb+c+1]*W[(size_t)(cb+c+1)*KDIM+tx];
                p2 += hs[ty][cb+c+2]*W[(size_t)(cb+c+2)*KDIM+tx];
                p3 += hs[ty][cb+c+3]*W[(size_t)(cb+c+3)*KDIM+tx];
            }
            float part = (p0+p1)+(p2+p3);
            if (e == 1) red[ty][tx] = part;
            __syncthreads();
            if (e == 0) acc += (s ? (1.f/3.f) : 1.f) * (part + red[ty][tx]);
        }
    __syncthreads();
    if (e == 0){
        float r = 1.f/(1.f+expf(-acc));
        size_t di = (size_t)(b0+ty)*KDIM + tx;
        float dn = dstate[di]*r;
        dstate[di] = dn;
        dsm[ty][tx] = dn;
    }
    __syncthreads();
    int dd = tid;
    for (int r = 0; r < 4; r++){
        int b = b0 + r;
        float s0=0.f,s1=0.f,s2=0.f,s3=0.f;
#pragma unroll
        for (int k = 0; k < KDIM; k += 4){
            s0 += dsm[r][k]  *wd[(size_t)k*DDIM+dd];
            s1 += dsm[r][k+1]*wd[(size_t)(k+1)*DDIM+dd];
            s2 += dsm[r][k+2]*wd[(size_t)(k+2)*DDIM+dd];
            s3 += dsm[r][k+3]*wd[(size_t)(k+3)*DDIM+dd];
        }
        float dwd = tanhf((s0+s1)+(s2+s3));
        const float* g = gate + (size_t)b*G4D;
        float gf = g[dd], gi = g[DDIM+dd], go = g[2*DDIM+dd], gc = g[3*DDIM+dd];
        if (whg){
            const float* w = whg + (size_t)b*G4D;
            gf += w[dd]; gi += w[DDIM+dd]; go += w[2*DDIM+dd]; gc += w[3*DDIM+dd];
        }
        float f  = 1.f/(1.f+expf(-gf));
        float ii = 1.f/(1.f+expf(-gi));
        float o  = 1.f/(1.f+expf(-go));
        float cb = tanhf(gc);
        size_t ci = (size_t)b*DDIM + dd;
        float c = f*cst[ci] + ii*cb + dwd;
        cst[ci] = c;
        float h = o*tanhf(c);
        size_t ho = (size_t)b*HW + dd;
        hout[ho] = h;
        bf16 hb = __float2bfloat16(h);
        hh[ho] = hb; hl[ho] = __float2bfloat16(h - __bfloat162float(hb));
    }
}

// ---- host ----
extern "C" void kernel_launch(void* const* d_in, const int* in_sizes, int n_in,
                              void* d_out, int out_size)
{
    (void)n_in; (void)out_size;
    const float* inputs    = (const float*)d_in[0];
    const float* init_keys = (const float*)d_in[1];
    const float *wx[NL], *wxb[NL], *whb[NL], *wr[NL], *wl[NL], *wh[NL];
    bool dict_order = (in_sizes[4] == 1048576);
    if (dict_order){
        for (int l = 0; l < NL; l++){
            int b0 = 2 + l*6;
            wx[l]=(const float*)d_in[b0];   wxb[l]=(const float*)d_in[b0+1];
            wh[l]=(const float*)d_in[b0+2]; whb[l]=(const float*)d_in[b0+3];
            wr[l]=(const float*)d_in[b0+4]; wl[l]=(const float*)d_in[b0+5];
        }
    } else {
        for (int l = 0; l < NL; l++){
            wx[l]=(const float*)d_in[2+2*l]; wxb[l]=(const float*)d_in[3+2*l];
            wh[l]=(const float*)d_in[8+2*l]; whb[l]=(const float*)d_in[9+2*l];
            wr[l]=(const float*)d_in[14+l];  wl[l]=(const float*)d_in[17+l];
        }
    }
    const float* wd    = (const float*)d_in[20];
    const float* projw = (const float*)d_in[21];
    const float* projb = (const float*)d_in[22];
    float* out = (float*)d_out;

    float *pregate,*whbuf,*prer,*hall,*cst,*dst;
    bf16 *hh,*hl,*xh,*xl,*pwh,*pwl;
    cudaGetSymbolAddress((void**)&pregate, g_pregate);
    cudaGetSymbolAddress((void**)&whbuf, g_whbuf);
    cudaGetSymbolAddress((void**)&prer, g_prer);
    cudaGetSymbolAddress((void**)&hall, g_hall);
    cudaGetSymbolAddress((void**)&cst, g_c);
    cudaGetSymbolAddress((void**)&dst, g_d);
    cudaGetSymbolAddress((void**)&hh, g_hh);
    cudaGetSymbolAddress((void**)&hl, g_hl);
    cudaGetSymbolAddress((void**)&xh, g_xh);
    cudaGetSymbolAddress((void**)&xl, g_xl);
    cudaGetSymbolAddress((void**)&pwh, g_pwh);
    cudaGetSymbolAddress((void**)&pwl, g_pwl);

    // one-time stream/event creation (host resources only; no device memory)
    static cudaStream_t s2 = nullptr;
    static cudaEvent_t evk[3], evw[3];
    if (!s2){
        cudaStreamCreateWithFlags(&s2, cudaStreamNonBlocking);
        for (int i = 0; i < 3; i++){
            cudaEventCreateWithFlags(&evk[i], cudaEventDisableTiming);
            cudaEventCreateWithFlags(&evw[i], cudaEventDisableTiming);
        }
    }

    cudaFuncSetAttribute(tgemm_kernel, cudaFuncAttributeMaxDynamicSharedMemorySize, DSMEM);

    init_kernel<<<(BATCH*HW + 255)/256, 256>>>(init_keys);
    xsplit_kernel<<<(BATCH*TSTEPS*CDIM + 255)/256, 256>>>(inputs, xh, xl, BATCH*TSTEPS*CDIM);

    const uint32_t offwx[3] = {OFF_WX0, OFF_WX1, OFF_WX2};
    const int fin[3] = {512, 1024, 1536};
    dim3 wb(32, 8);
    for (int l = 0; l < NL; l++){
        wsplit_kernel<<<dim3(64, fin[l]/32), wb>>>(wx[l], pwh+offwx[l], pwl+offwx[l], fin[l], 2048);
        wsplit_kernel<<<dim3(64, 16), wb>>>(wh[l], pwh+OFF_WH0+l*1048576u, pwl+OFF_WH0+l*1048576u, 512, 2048);
        wsplit_kernel<<<dim3(2, 16), wb>>>(wr[l], pwh+OFF_WR+l*32768u, pwl+OFF_WR+l*32768u, 512, 64);
    }
    wsplit_kernel<<<dim3(16, 48), wb>>>(projw, pwh+OFF_PROJ, pwl+OFF_PROJ, 1536, 512);

    const int MBT = BATCH*TSTEPS;
    const long long SLAB = (long long)TSTEPS*BATCH*G4D;
    for (int l = 0; l < NL; l++)
        tgemm_kernel<<<dim3(16, MBT/128, 1), 512, DSMEM>>>(
            xh, xl, pwh+offwx[l], pwl+offwx[l], nullptr,nullptr,0, 0,0,0,
            512, 512, fin[l], pregate + (size_t)l*SLAB, G4D,
            wxb[l], whb[l], 1, TSTEPS, BATCH);
    tgemm_kernel<<<dim3(2, MBT/128, 1), 512, DSMEM>>>(
        xh, xl, pwh+OFF_WR, pwl+OFF_WR, nullptr,nullptr,0, 0,0,0,
        512, 512, 512, prer, 256, nullptr, nullptr, 1, TSTEPS, BATCH);

    // sequential recurrence; wh GEMMs run on s2, decoupled via whbuf + events
    for (int t = 0; t < TSTEPS; t++){
        float* ha_c = hall + (size_t)(t+1)*BATCH*HW;
        float* ha_p = hall + (size_t)t*BATCH*HW;
        bf16* hh_c = hh + (size_t)(t+1)*BATCH*HW; bf16* hl_c = hl + (size_t)(t+1)*BATCH*HW;
        float* gate_t = pregate + (size_t)t*BATCH*G4D;

        for (int l = 0; l < NL; l++){
            if (l == 1)      // z0: h0@wx1[C:] -> slab1 ; z1: h0@wx2[C:C+512] -> slab2
                tgemm_kernel<<<dim3(16, 4, 2), 512, DSMEM>>>(
                    hh_c, hl_c, pwh+OFF_WX1+CDIM, pwl+OFF_WX1+CDIM,
                    pwh+OFF_WX2+CDIM, pwl+OFF_WX2+CDIM, 1536,
                    0, 0, SLAB,
                    512, HW, 1024, gate_t + 1*SLAB, G4D, nullptr, nullptr, 0, 0, 0);
            else if (l == 2) // h1@wx2[C+512:] -> slab2
                tgemm_kernel<<<dim3(16, 4, 1), 512, DSMEM>>>(
                    hh_c + 512, hl_c + 512, pwh+OFF_WX2+CDIM+512, pwl+OFF_WX2+CDIM+512,
                    nullptr,nullptr,0, 0,0,0,
                    512, HW, 1536, gate_t + 2*SLAB, G4D, nullptr, nullptr, 0, 0, 0);
            if (t > 0) cudaStreamWaitEvent(0, evw[l], 0);
            k12_kernel<<<BATCH/4, 512>>>(
                l, prer + (size_t)t*BATCH*256 + l*64, ha_c, ha_p,
                wr[l], wl[0], wl[1],
                gate_t + (size_t)l*SLAB, (t > 0) ? (whbuf + (size_t)l*BATCH*G4D) : nullptr,
                wd,
                cst + (size_t)l*BATCH*DDIM, dst + (size_t)l*BATCH*KDIM,
                ha_c + l*DDIM, hh_c + l*DDIM, hl_c + l*DDIM);
            if (t + 1 < TSTEPS){
                cudaEventRecord(evk[l], 0);
                cudaStreamWaitEvent(s2, evk[l], 0);
                tgemm_kernel<<<dim3(16, 4, 1), 512, DSMEM, s2>>>(
                    hh_c + l*DDIM, hl_c + l*DDIM,
                    pwh+OFF_WH0+(size_t)l*1048576u, pwl+OFF_WH0+(size_t)l*1048576u,
                    nullptr,nullptr,0, 0,0,0,
                    512, HW, 512, whbuf + (size_t)l*BATCH*G4D, G4D,
                    nullptr, nullptr, 1, BATCH, 1);
                cudaEventRecord(evw[l], s2);
            }
        }
    }

    // projection (rows t*B+b -> out[b][t][:])
    tgemm_kernel<<<dim3(4, MBT/128, 1), 512, DSMEM>>>(
        hh + (size_t)BATCH*HW, hl + (size_t)BATCH*HW, pwh+OFF_PROJ, pwl+OFF_PROJ,
        nullptr,nullptr,0, 0,0,0,
        1536, HW, 1536, out, 512, projb, nullptr, 1, BATCH, TSTEPS);
}